// round 13
// baseline (speedup 1.0000x reference)
#include <cuda_runtime.h>
#include <cuda_fp16.h>
#include <cstdint>

#define B_  2
#define T_  2048
#define C_  1024
#define H_  16
#define M_  (B_*T_)      // 4096
#define NQKV_ (3*C_)     // 3072

// ---------------- device scratch (no allocation allowed) -------------------
__device__ __half g_xh[M_*C_];                       // x fp16
__device__ __half g_wqkvTh[NQKV_*C_];                // Wqkv^T fp16
__device__ __half g_woutTh[C_*C_];                   // Wout^T fp16
__device__ __half g_attnh[M_*C_];                    // attn out fp16
// [b,h,t,d]: q pre-scaled by 0.125*log2(e), k, v fp16
__device__ __half g_qh[M_*C_], g_kh[M_*C_], g_vh[M_*C_];

// ---------------- helpers ----------------------------------------------------
__device__ __forceinline__ uint32_t smem_u32_of(const void* p) {
    uint32_t a;
    asm("{ .reg .u64 t; cvta.to.shared.u64 t, %1; cvt.u32.u64 %0, t; }" : "=r"(a) : "l"(p));
    return a;
}
__device__ __forceinline__ void ldsm4(uint32_t* r, uint32_t addr) {
    asm volatile("ldmatrix.sync.aligned.m8n8.x4.shared.b16 {%0,%1,%2,%3}, [%4];"
                 : "=r"(r[0]), "=r"(r[1]), "=r"(r[2]), "=r"(r[3]) : "r"(addr));
}
__device__ __forceinline__ void ldsm4t(uint32_t* r, uint32_t addr) {
    asm volatile("ldmatrix.sync.aligned.m8n8.x4.trans.shared.b16 {%0,%1,%2,%3}, [%4];"
                 : "=r"(r[0]), "=r"(r[1]), "=r"(r[2]), "=r"(r[3]) : "r"(addr));
}
__device__ __forceinline__ void mma16816(float* c, const uint32_t* a,
                                         uint32_t b0, uint32_t b1) {
    asm volatile(
        "mma.sync.aligned.m16n8k16.row.col.f32.f16.f16.f32 "
        "{%0,%1,%2,%3}, {%4,%5,%6,%7}, {%8,%9}, {%0,%1,%2,%3};"
        : "+f"(c[0]), "+f"(c[1]), "+f"(c[2]), "+f"(c[3])
        : "r"(a[0]), "r"(a[1]), "r"(a[2]), "r"(a[3]), "r"(b0), "r"(b1));
}
#define CP16(dst, src) \
    asm volatile("cp.async.cg.shared.global [%0], [%1], 16;" :: "r"(dst), "l"(src) : "memory")
#define CP_COMMIT() asm volatile("cp.async.commit_group;" ::: "memory")
#define CP_WAIT0()  asm volatile("cp.async.wait_group 0;" ::: "memory")

__device__ __forceinline__ uint32_t sw128(uint32_t off) {
    return off ^ ((off >> 3) & 0x70);
}
__device__ __forceinline__ uint32_t pack_h2(float v0, float v1) {
    __half2 hp = __floats2half2_rn(v0, v1);
    return *(uint32_t*)&hp;
}
__device__ __forceinline__ uint32_t ex2_h2(uint32_t x) {
    uint32_t r;
    asm("ex2.approx.f16x2 %0, %1;" : "=r"(r) : "r"(x));
    return r;
}

// ---------------------------------------------------------------------------
// fp16 1-term HMMA GEMM: D = A_fp16 * B_fp16.
// CTA 128x128, 8 warps (4x2), warp tile 32x64, K-chunk 64 (SW128), 2 stages,
// one __syncthreads per chunk.
// ---------------------------------------------------------------------------
#define GS_A    0
#define GS_B    16384
#define GS_STAGE 32768
#define GEMM_SMEM 65536
#define NCHUNK 16

__device__ __forceinline__ void gemm_load_stage(
    uint32_t dst, int ch, int bm, int bn, int tid,
    const __half* Ah, const __half* Bh) {
    const int k0 = ch * 64;
#pragma unroll
    for (int i = tid; i < 1024; i += 256) {
        int r = i >> 3, g = i & 7;
        uint32_t sw = sw128((uint32_t)(r * 128 + g * 16));
        CP16(dst + GS_A + sw, Ah + (size_t)(bm + r) * C_ + k0 + g * 8);
        CP16(dst + GS_B + sw, Bh + (size_t)(bn + r) * C_ + k0 + g * 8);
    }
}

__global__ __launch_bounds__(256, 2) void hmma_gemm(int mode, float* __restrict__ out,
                                                    const float* __restrict__ bias, int N) {
    extern __shared__ char smem[];
    const uint32_t sbase = smem_u32_of(smem);
    const int tid = threadIdx.x, wid = tid >> 5, lane = tid & 31;
    const int bm = blockIdx.y * 128, bn = blockIdx.x * 128;
    const int wm = wid & 3, wn = wid >> 2;

    const __half* Ah = (mode == 0) ? g_xh : g_attnh;
    const __half* Bh = (mode == 0) ? g_wqkvTh : g_woutTh;

    float acc[2][8][4];
#pragma unroll
    for (int i = 0; i < 2; i++)
#pragma unroll
        for (int j = 0; j < 8; j++)
#pragma unroll
            for (int k = 0; k < 4; k++) acc[i][j][k] = 0.0f;

    const int lrow = lane & 15;
    const int lkb  = (lane >> 4) << 4;

    gemm_load_stage(sbase, 0, bm, bn, tid, Ah, Bh);
    CP_COMMIT();
    CP_WAIT0();
    __syncthreads();

    for (int ch = 0; ch < NCHUNK; ch++) {
        if (ch + 1 < NCHUNK) {
            gemm_load_stage(sbase + (uint32_t)((ch + 1) & 1) * GS_STAGE, ch + 1,
                            bm, bn, tid, Ah, Bh);
            CP_COMMIT();
        }
        const uint32_t buf = sbase + (uint32_t)(ch & 1) * GS_STAGE;

#pragma unroll
        for (int ks = 0; ks < 4; ks++) {
            uint32_t ah[2][4];
#pragma unroll
            for (int mf = 0; mf < 2; mf++) {
                uint32_t sw = sw128((uint32_t)((wm * 32 + mf * 16 + lrow) * 128 + ks * 32 + lkb));
                ldsm4(ah[mf], buf + GS_A + sw);
            }
#pragma unroll
            for (int np = 0; np < 4; np++) {
                uint32_t sw = sw128((uint32_t)((wn * 64 + np * 16 + lrow) * 128 + ks * 32 + lkb));
                uint32_t bh[4];
                ldsm4(bh, buf + GS_B + sw);
#pragma unroll
                for (int mf = 0; mf < 2; mf++) {
                    mma16816(acc[mf][np * 2],     ah[mf], bh[0], bh[2]);
                    mma16816(acc[mf][np * 2 + 1], ah[mf], bh[1], bh[3]);
                }
            }
        }
        CP_WAIT0();
        __syncthreads();
    }

    const int r0 = bm + wm * 32 + (lane >> 2);
    const int c0 = bn + wn * 64 + (lane & 3) * 2;
    if (mode == 0) {
#pragma unroll
        for (int nf = 0; nf < 8; nf++) {
            int col = c0 + nf * 8;
            int which = col >> 10;
            int hh = (col >> 6) & 15;
            int d = col & 63;
            // q pre-scaled by (1/8)*log2(e) for log2-domain softmax
            float sc = (which == 0) ? 0.18033688011112042f : 1.0f;
            __half* dst = (which == 0) ? g_qh : (which == 1) ? g_kh : g_vh;
#pragma unroll
            for (int mf = 0; mf < 2; mf++) {
                int row = r0 + mf * 16;
                int t = row & (T_ - 1), b = row >> 11;
                size_t i1 = ((size_t)((b << 4) + hh) * T_ + t) * 64 + d;
                *(uint32_t*)&dst[i1] = pack_h2(acc[mf][nf][0] * sc, acc[mf][nf][1] * sc);
                *(uint32_t*)&dst[i1 + 8 * 64] = pack_h2(acc[mf][nf][2] * sc, acc[mf][nf][3] * sc);
            }
        }
    } else {
#pragma unroll
        for (int mf = 0; mf < 2; mf++) {
#pragma unroll
            for (int nf = 0; nf < 8; nf++) {
                int row = r0 + mf * 16;
                int col = c0 + nf * 8;
                float b0 = bias[col], b1 = bias[col + 1];
                *(float2*)&out[(size_t)row * N + col] =
                    make_float2(acc[mf][nf][0] + b0, acc[mf][nf][1] + b1);
                *(float2*)&out[(size_t)(row + 8) * N + col] =
                    make_float2(acc[mf][nf][2] + b0, acc[mf][nf][3] + b1);
            }
        }
    }
}

// ---------------------------------------------------------------------------
__global__ void conv_x(const float* __restrict__ src) {
    int i = blockIdx.x * 256 + threadIdx.x;
    if (i < M_ * C_) g_xh[i] = __float2half(src[i]);
}
__global__ void conv_t2(const float* __restrict__ wqkv, const float* __restrict__ wout) {
    __shared__ float s[32][33];
    const int z = blockIdx.z;
    const int N = z ? C_ : NQKV_;
    if (blockIdx.x * 32 >= N) return;
    const float* src = z ? wout : wqkv;
    __half* dst = z ? g_woutTh : g_wqkvTh;
    int n0 = blockIdx.x * 32, k0 = blockIdx.y * 32;
    int tx = threadIdx.x, ty = threadIdx.y;
#pragma unroll
    for (int yy = 0; yy < 32; yy += 8)
        s[ty + yy][tx] = src[(size_t)(k0 + ty + yy) * N + n0 + tx];
    __syncthreads();
#pragma unroll
    for (int yy = 0; yy < 32; yy += 8)
        dst[(size_t)(n0 + ty + yy) * C_ + k0 + tx] = __float2half(s[tx][ty + yy]);
}

// ---------------------------------------------------------------------------
// fp16 flash attention, log2-domain softmax:
//  - S already in log2 units (q pre-scaled by 0.125*log2e)
//  - p = ex2.f16x2(s - m);  rescale factors via exp2f
//  - conditional rescale skip (max rarely increases)
//  - fully-masked warps skip compute on the last key-tiles
//  - MMA row-sums via ones-fragment; one __syncthreads per key-tile
// ---------------------------------------------------------------------------
#define FLS_KH 0
#define FLS_VH 8192
#define FLS_STAGE 16384
#define FLS_QH 32768
#define FL_SMEM 49152

__device__ __forceinline__ void fl_load_tile(uint32_t dst, size_t gbase, int kt, int tid) {
    const __half* kh = g_kh + gbase + (size_t)kt * 64 * 64;
    const __half* vh = g_vh + gbase + (size_t)kt * 64 * 64;
#pragma unroll
    for (int i = tid; i < 512; i += 256) {
        int r = i >> 3, g = i & 7;
        uint32_t sw = sw128((uint32_t)(r * 128 + g * 16));
        size_t go = (size_t)r * 64 + g * 8;
        CP16(dst + FLS_KH + sw, kh + go);
        CP16(dst + FLS_VH + sw, vh + go);
    }
}

__global__ __launch_bounds__(256, 2) void hmma_flash() {
    extern __shared__ char smem[];
    const uint32_t sbase = smem_u32_of(smem);
    const int tid = threadIdx.x, w = tid >> 5, lane = tid & 31;
    const int qt = gridDim.x - 1 - blockIdx.x;   // heavy tiles first
    const int bh = blockIdx.y;
    const int nkt = 2 * (qt + 1);
    const size_t gbase = (size_t)bh * T_ * 64;
    const int lrow = lane & 15, lkb = (lane >> 4) << 4;
    const uint32_t ones = (lane < 4) ? 0x3C003C00u : 0u;  // B col0 = 1

    {
        const __half* qh = g_qh + gbase + (size_t)qt * 128 * 64;
#pragma unroll
        for (int i = tid; i < 1024; i += 256) {
            int r = i >> 3, g = i & 7;
            uint32_t sw = sw128((uint32_t)(r * 128 + g * 16));
            CP16(sbase + FLS_QH + sw, qh + (size_t)r * 64 + g * 8);
        }
    }
    fl_load_tile(sbase, gbase, 0, tid);
    CP_COMMIT();
    CP_WAIT0();
    __syncthreads();

    uint32_t qf[4][4];
#pragma unroll
    for (int ks = 0; ks < 4; ks++) {
        uint32_t sw = sw128((uint32_t)((w * 16 + lrow) * 128 + ks * 32 + lkb));
        ldsm4(qf[ks], sbase + FLS_QH + sw);
    }

    float o[8][4];
#pragma unroll
    for (int j = 0; j < 8; j++)
#pragma unroll
        for (int k = 0; k < 4; k++) o[j][k] = 0.0f;
    float m1 = -1e30f, m2 = -1e30f, l1 = 0.0f, l2 = 0.0f;

    const int wrow_max = qt * 128 + w * 16 + 15;   // last q row this warp owns

    for (int kt = 0; kt < nkt; kt++) {
        if (kt + 1 < nkt) {
            fl_load_tile(sbase + (uint32_t)((kt + 1) & 1) * FLS_STAGE, gbase, kt + 1, tid);
            CP_COMMIT();
        }
        const uint32_t buf = sbase + (uint32_t)(kt & 1) * FLS_STAGE;

        if (kt * 64 <= wrow_max) {   // warp has at least one unmasked key
            // ---- S (log2 units) = (Q*0.125*log2e) K^T
            float s[8][4];
#pragma unroll
            for (int j = 0; j < 8; j++)
#pragma unroll
                for (int k = 0; k < 4; k++) s[j][k] = 0.0f;
#pragma unroll
            for (int kn = 0; kn < 4; kn++) {
#pragma unroll
                for (int ks = 0; ks < 4; ks++) {
                    uint32_t sw = sw128((uint32_t)((kn * 16 + lrow) * 128 + ks * 32 + lkb));
                    uint32_t kh4[4];
                    ldsm4(kh4, buf + FLS_KH + sw);
                    mma16816(s[kn * 2],     qf[ks], kh4[0], kh4[2]);
                    mma16816(s[kn * 2 + 1], qf[ks], kh4[1], kh4[3]);
                }
            }

            // ---- causal mask
            const int gr1 = qt * 128 + w * 16 + (lane >> 2);
            if (kt * 64 + 63 > qt * 128 + w * 16) {
#pragma unroll
                for (int j = 0; j < 8; j++) {
                    int c = kt * 64 + j * 8 + (lane & 3) * 2;
                    if (c     > gr1)     s[j][0] = -1e30f;
                    if (c + 1 > gr1)     s[j][1] = -1e30f;
                    if (c     > gr1 + 8) s[j][2] = -1e30f;
                    if (c + 1 > gr1 + 8) s[j][3] = -1e30f;
                }
            }

            // ---- online max (log2 domain)
            float mx1 = -1e30f, mx2 = -1e30f;
#pragma unroll
            for (int j = 0; j < 8; j++) {
                mx1 = fmaxf(mx1, fmaxf(s[j][0], s[j][1]));
                mx2 = fmaxf(mx2, fmaxf(s[j][2], s[j][3]));
            }
            mx1 = fmaxf(mx1, __shfl_xor_sync(0xffffffffu, mx1, 1));
            mx1 = fmaxf(mx1, __shfl_xor_sync(0xffffffffu, mx1, 2));
            mx2 = fmaxf(mx2, __shfl_xor_sync(0xffffffffu, mx2, 1));
            mx2 = fmaxf(mx2, __shfl_xor_sync(0xffffffffu, mx2, 2));
            float nm1 = fmaxf(m1, mx1), nm2 = fmaxf(m2, mx2);
            // rescale only if any lane's max increased (warp-uniform branch)
            if (__any_sync(0xffffffffu, (nm1 > m1) || (nm2 > m2))) {
                float a1 = exp2f(m1 - nm1), a2 = exp2f(m2 - nm2);
                m1 = nm1; m2 = nm2;
#pragma unroll
                for (int j = 0; j < 8; j++) {
                    o[j][0] *= a1; o[j][1] *= a1;
                    o[j][2] *= a2; o[j][3] *= a2;
                }
                l1 *= a1; l2 *= a2;
            }

            // ---- p = ex2(s - m); O += P V; row sums via ones-MMA
            float osum[4] = {0.0f, 0.0f, 0.0f, 0.0f};
            const int lg = lane >> 3, lr8 = lane & 7;
#pragma unroll
            for (int kn = 0; kn < 4; kn++) {
                uint32_t ph[4];
                ph[0] = ex2_h2(pack_h2(s[2 * kn][0] - m1, s[2 * kn][1] - m1));
                ph[1] = ex2_h2(pack_h2(s[2 * kn][2] - m2, s[2 * kn][3] - m2));
                ph[2] = ex2_h2(pack_h2(s[2 * kn + 1][0] - m1, s[2 * kn + 1][1] - m1));
                ph[3] = ex2_h2(pack_h2(s[2 * kn + 1][2] - m2, s[2 * kn + 1][3] - m2));
                mma16816(osum, ph, ones, ones);
#pragma unroll
                for (int nd = 0; nd < 4; nd++) {
                    int key = kn * 16 + lr8 + (lg >> 1) * 8;
                    int dim = nd * 16 + (lg & 1) * 8;
                    uint32_t sw = sw128((uint32_t)(key * 128 + dim * 2));
                    uint32_t vh4[4];
                    ldsm4t(vh4, buf + FLS_VH + sw);
                    mma16816(o[nd * 2],     ph, vh4[0], vh4[2]);
                    mma16816(o[nd * 2 + 1], ph, vh4[1], vh4[3]);
                }
            }
            l1 += osum[0];
            l2 += osum[2];
        }

        CP_WAIT0();
        __syncthreads();
    }

    l1 = __shfl_sync(0xffffffffu, l1, lane & 28);
    l2 = __shfl_sync(0xffffffffu, l2, lane & 28);

    const int b = bh >> 4, hh = bh & 15;
    const int t1 = qt * 128 + w * 16 + (lane >> 2);
    const float inv1 = 1.0f / l1, inv2 = 1.0f / l2;
#pragma unroll
    for (int j = 0; j < 8; j++) {
        int d = j * 8 + (lane & 3) * 2;
        size_t i1 = ((size_t)(b * T_ + t1)) * C_ + hh * 64 + d;
        size_t i2 = i1 + (size_t)8 * C_;
        *(uint32_t*)&g_attnh[i1] = pack_h2(o[j][0] * inv1, o[j][1] * inv1);
        *(uint32_t*)&g_attnh[i2] = pack_h2(o[j][2] * inv2, o[j][3] * inv2);
    }
}

// ---------------------------------------------------------------------------
extern "C" void kernel_launch(void* const* d_in, const int* in_sizes, int n_in,
                              void* d_out, int out_size) {
    const float* x    = (const float*)d_in[0];
    const float* Wqkv = (const float*)d_in[1];
    const float* Wout = (const float*)d_in[2];
    const float* bout = (const float*)d_in[3];
    float* out = (float*)d_out;

    conv_x<<<(M_ * C_ + 255) / 256, 256>>>(x);
    conv_t2<<<dim3(NQKV_ / 32, C_ / 32, 2), dim3(32, 8)>>>(Wqkv, Wout);

    cudaFuncSetAttribute(hmma_gemm, cudaFuncAttributeMaxDynamicSharedMemorySize, GEMM_SMEM);
    hmma_gemm<<<dim3(NQKV_ / 128, M_ / 128), 256, GEMM_SMEM>>>(0, nullptr, nullptr, NQKV_);

    cudaFuncSetAttribute(hmma_flash, cudaFuncAttributeMaxDynamicSharedMemorySize, FL_SMEM);
    hmma_flash<<<dim3(T_ / 128, B_ * H_), 256, FL_SMEM>>>();

    hmma_gemm<<<dim3(C_ / 128, M_ / 128), 256, GEMM_SMEM>>>(1, out, bout, C_);
}

// round 14
// speedup vs baseline: 1.0464x; 1.0464x over previous
#include <cuda_runtime.h>
#include <cuda_fp16.h>
#include <cstdint>

#define B_  2
#define T_  2048
#define C_  1024
#define H_  16
#define M_  (B_*T_)      // 4096
#define NQKV_ (3*C_)     // 3072

// ---------------- device scratch (no allocation allowed) -------------------
__device__ __half g_xh[M_*C_];                       // x fp16
__device__ __half g_wqkvTh[NQKV_*C_];                // Wqkv^T fp16
__device__ __half g_woutTh[C_*C_];                   // Wout^T fp16
__device__ __half g_attnh[M_*C_];                    // attn out fp16
// [b,h,t,d]: q pre-scaled by 0.125*log2(e), k, v fp16
__device__ __half g_qh[M_*C_], g_kh[M_*C_], g_vh[M_*C_];

// ---------------- helpers ----------------------------------------------------
__device__ __forceinline__ uint32_t smem_u32_of(const void* p) {
    uint32_t a;
    asm("{ .reg .u64 t; cvta.to.shared.u64 t, %1; cvt.u32.u64 %0, t; }" : "=r"(a) : "l"(p));
    return a;
}
__device__ __forceinline__ void ldsm4(uint32_t* r, uint32_t addr) {
    asm volatile("ldmatrix.sync.aligned.m8n8.x4.shared.b16 {%0,%1,%2,%3}, [%4];"
                 : "=r"(r[0]), "=r"(r[1]), "=r"(r[2]), "=r"(r[3]) : "r"(addr));
}
__device__ __forceinline__ void ldsm4t(uint32_t* r, uint32_t addr) {
    asm volatile("ldmatrix.sync.aligned.m8n8.x4.trans.shared.b16 {%0,%1,%2,%3}, [%4];"
                 : "=r"(r[0]), "=r"(r[1]), "=r"(r[2]), "=r"(r[3]) : "r"(addr));
}
__device__ __forceinline__ void mma16816(float* c, const uint32_t* a,
                                         uint32_t b0, uint32_t b1) {
    asm volatile(
        "mma.sync.aligned.m16n8k16.row.col.f32.f16.f16.f32 "
        "{%0,%1,%2,%3}, {%4,%5,%6,%7}, {%8,%9}, {%0,%1,%2,%3};"
        : "+f"(c[0]), "+f"(c[1]), "+f"(c[2]), "+f"(c[3])
        : "r"(a[0]), "r"(a[1]), "r"(a[2]), "r"(a[3]), "r"(b0), "r"(b1));
}
#define CP16(dst, src) \
    asm volatile("cp.async.cg.shared.global [%0], [%1], 16;" :: "r"(dst), "l"(src) : "memory")
#define CP_COMMIT() asm volatile("cp.async.commit_group;" ::: "memory")
#define CP_WAIT0()  asm volatile("cp.async.wait_group 0;" ::: "memory")

__device__ __forceinline__ uint32_t sw128(uint32_t off) {
    return off ^ ((off >> 3) & 0x70);
}
__device__ __forceinline__ uint32_t pack_h2(float v0, float v1) {
    __half2 hp = __floats2half2_rn(v0, v1);
    return *(uint32_t*)&hp;
}
__device__ __forceinline__ uint32_t ex2_h2(uint32_t x) {
    uint32_t r;
    asm("ex2.approx.f16x2 %0, %1;" : "=r"(r) : "r"(x));
    return r;
}

// ---------------------------------------------------------------------------
// fp16 1-term HMMA GEMM: D = A_fp16 * B_fp16.  (unchanged from round 13)
// CTA 128x128, 8 warps (4x2), warp tile 32x64, K-chunk 64 (SW128), 2 stages,
// one __syncthreads per chunk.
// ---------------------------------------------------------------------------
#define GS_A    0
#define GS_B    16384
#define GS_STAGE 32768
#define GEMM_SMEM 65536
#define NCHUNK 16

__device__ __forceinline__ void gemm_load_stage(
    uint32_t dst, int ch, int bm, int bn, int tid,
    const __half* Ah, const __half* Bh) {
    const int k0 = ch * 64;
#pragma unroll
    for (int i = tid; i < 1024; i += 256) {
        int r = i >> 3, g = i & 7;
        uint32_t sw = sw128((uint32_t)(r * 128 + g * 16));
        CP16(dst + GS_A + sw, Ah + (size_t)(bm + r) * C_ + k0 + g * 8);
        CP16(dst + GS_B + sw, Bh + (size_t)(bn + r) * C_ + k0 + g * 8);
    }
}

__global__ __launch_bounds__(256, 2) void hmma_gemm(int mode, float* __restrict__ out,
                                                    const float* __restrict__ bias, int N) {
    extern __shared__ char smem[];
    const uint32_t sbase = smem_u32_of(smem);
    const int tid = threadIdx.x, wid = tid >> 5, lane = tid & 31;
    const int bm = blockIdx.y * 128, bn = blockIdx.x * 128;
    const int wm = wid & 3, wn = wid >> 2;

    const __half* Ah = (mode == 0) ? g_xh : g_attnh;
    const __half* Bh = (mode == 0) ? g_wqkvTh : g_woutTh;

    float acc[2][8][4];
#pragma unroll
    for (int i = 0; i < 2; i++)
#pragma unroll
        for (int j = 0; j < 8; j++)
#pragma unroll
            for (int k = 0; k < 4; k++) acc[i][j][k] = 0.0f;

    const int lrow = lane & 15;
    const int lkb  = (lane >> 4) << 4;

    gemm_load_stage(sbase, 0, bm, bn, tid, Ah, Bh);
    CP_COMMIT();
    CP_WAIT0();
    __syncthreads();

    for (int ch = 0; ch < NCHUNK; ch++) {
        if (ch + 1 < NCHUNK) {
            gemm_load_stage(sbase + (uint32_t)((ch + 1) & 1) * GS_STAGE, ch + 1,
                            bm, bn, tid, Ah, Bh);
            CP_COMMIT();
        }
        const uint32_t buf = sbase + (uint32_t)(ch & 1) * GS_STAGE;

#pragma unroll
        for (int ks = 0; ks < 4; ks++) {
            uint32_t ah[2][4];
#pragma unroll
            for (int mf = 0; mf < 2; mf++) {
                uint32_t sw = sw128((uint32_t)((wm * 32 + mf * 16 + lrow) * 128 + ks * 32 + lkb));
                ldsm4(ah[mf], buf + GS_A + sw);
            }
#pragma unroll
            for (int np = 0; np < 4; np++) {
                uint32_t sw = sw128((uint32_t)((wn * 64 + np * 16 + lrow) * 128 + ks * 32 + lkb));
                uint32_t bh[4];
                ldsm4(bh, buf + GS_B + sw);
#pragma unroll
                for (int mf = 0; mf < 2; mf++) {
                    mma16816(acc[mf][np * 2],     ah[mf], bh[0], bh[2]);
                    mma16816(acc[mf][np * 2 + 1], ah[mf], bh[1], bh[3]);
                }
            }
        }
        CP_WAIT0();
        __syncthreads();
    }

    const int r0 = bm + wm * 32 + (lane >> 2);
    const int c0 = bn + wn * 64 + (lane & 3) * 2;
    if (mode == 0) {
#pragma unroll
        for (int nf = 0; nf < 8; nf++) {
            int col = c0 + nf * 8;
            int which = col >> 10;
            int hh = (col >> 6) & 15;
            int d = col & 63;
            // q pre-scaled by (1/8)*log2(e) for log2-domain softmax
            float sc = (which == 0) ? 0.18033688011112042f : 1.0f;
            __half* dst = (which == 0) ? g_qh : (which == 1) ? g_kh : g_vh;
#pragma unroll
            for (int mf = 0; mf < 2; mf++) {
                int row = r0 + mf * 16;
                int t = row & (T_ - 1), b = row >> 11;
                size_t i1 = ((size_t)((b << 4) + hh) * T_ + t) * 64 + d;
                *(uint32_t*)&dst[i1] = pack_h2(acc[mf][nf][0] * sc, acc[mf][nf][1] * sc);
                *(uint32_t*)&dst[i1 + 8 * 64] = pack_h2(acc[mf][nf][2] * sc, acc[mf][nf][3] * sc);
            }
        }
    } else {
#pragma unroll
        for (int mf = 0; mf < 2; mf++) {
#pragma unroll
            for (int nf = 0; nf < 8; nf++) {
                int row = r0 + mf * 16;
                int col = c0 + nf * 8;
                float b0 = bias[col], b1 = bias[col + 1];
                *(float2*)&out[(size_t)row * N + col] =
                    make_float2(acc[mf][nf][0] + b0, acc[mf][nf][1] + b1);
                *(float2*)&out[(size_t)(row + 8) * N + col] =
                    make_float2(acc[mf][nf][2] + b0, acc[mf][nf][3] + b1);
            }
        }
    }
}

// ---------------------------------------------------------------------------
__global__ void conv_x(const float* __restrict__ src) {
    int i = blockIdx.x * 256 + threadIdx.x;
    if (i < M_ * C_) g_xh[i] = __float2half(src[i]);
}
__global__ void conv_t2(const float* __restrict__ wqkv, const float* __restrict__ wout) {
    __shared__ float s[32][33];
    const int z = blockIdx.z;
    const int N = z ? C_ : NQKV_;
    if (blockIdx.x * 32 >= N) return;
    const float* src = z ? wout : wqkv;
    __half* dst = z ? g_woutTh : g_wqkvTh;
    int n0 = blockIdx.x * 32, k0 = blockIdx.y * 32;
    int tx = threadIdx.x, ty = threadIdx.y;
#pragma unroll
    for (int yy = 0; yy < 32; yy += 8)
        s[ty + yy][tx] = src[(size_t)(k0 + ty + yy) * N + n0 + tx];
    __syncthreads();
#pragma unroll
    for (int yy = 0; yy < 32; yy += 8)
        dst[(size_t)(n0 + ty + yy) * C_ + k0 + tx] = __float2half(s[tx][ty + yy]);
}

// ---------------------------------------------------------------------------
// fp16 flash attention, log2-domain softmax, 128 keys per pipeline stage:
//   stage (32K) = [K64|V64|K64|V64]; 2 stages + Q(16K) = 80K; 2 CTA/SM.
//   One cp.async issue + one wait + one __syncthreads per 128 keys.
// ---------------------------------------------------------------------------
#define FLS_SUB   16384
#define FLS_VH    8192
#define FLS_STAGE 32768
#define FLS_QH    65536
#define FL_SMEM   81920

__device__ __forceinline__ void fl_load_pair(uint32_t dst, size_t gbase, int ktp, int tid) {
    const __half* kh = g_kh + gbase + (size_t)ktp * 128 * 64;
    const __half* vh = g_vh + gbase + (size_t)ktp * 128 * 64;
#pragma unroll
    for (int i = tid; i < 1024; i += 256) {
        int r = i >> 3, g = i & 7;           // r = 0..127 key row
        int sub = r >> 6, rr = r & 63;
        uint32_t sw = (uint32_t)sub * FLS_SUB + sw128((uint32_t)(rr * 128 + g * 16));
        size_t go = (size_t)r * 64 + g * 8;
        CP16(dst + sw, kh + go);
        CP16(dst + FLS_VH + sw, vh + go);
    }
}

__global__ __launch_bounds__(256, 2) void hmma_flash() {
    extern __shared__ char smem[];
    const uint32_t sbase = smem_u32_of(smem);
    const int tid = threadIdx.x, w = tid >> 5, lane = tid & 31;
    const int qt = gridDim.x - 1 - blockIdx.x;   // heavy tiles first
    const int bh = blockIdx.y;
    const int nktp = qt + 1;                      // 128-key pairs
    const size_t gbase = (size_t)bh * T_ * 64;
    const int lrow = lane & 15, lkb = (lane >> 4) << 4;
    const uint32_t ones = (lane < 4) ? 0x3C003C00u : 0u;  // B col0 = 1

    {
        const __half* qh = g_qh + gbase + (size_t)qt * 128 * 64;
#pragma unroll
        for (int i = tid; i < 1024; i += 256) {
            int r = i >> 3, g = i & 7;
            uint32_t sw = sw128((uint32_t)(r * 128 + g * 16));
            CP16(sbase + FLS_QH + sw, qh + (size_t)r * 64 + g * 8);
        }
    }
    fl_load_pair(sbase, gbase, 0, tid);
    CP_COMMIT();
    CP_WAIT0();
    __syncthreads();

    uint32_t qf[4][4];
#pragma unroll
    for (int ks = 0; ks < 4; ks++) {
        uint32_t sw = sw128((uint32_t)((w * 16 + lrow) * 128 + ks * 32 + lkb));
        ldsm4(qf[ks], sbase + FLS_QH + sw);
    }

    float o[8][4];
#pragma unroll
    for (int j = 0; j < 8; j++)
#pragma unroll
        for (int k = 0; k < 4; k++) o[j][k] = 0.0f;
    float m1 = -1e30f, m2 = -1e30f, l1 = 0.0f, l2 = 0.0f;

    const int wrow_max = qt * 128 + w * 16 + 15;   // last q row this warp owns

    for (int ktp = 0; ktp < nktp; ktp++) {
        if (ktp + 1 < nktp) {
            fl_load_pair(sbase + (uint32_t)((ktp + 1) & 1) * FLS_STAGE, gbase, ktp + 1, tid);
            CP_COMMIT();
        }
        const uint32_t stg = sbase + (uint32_t)(ktp & 1) * FLS_STAGE;

#pragma unroll
        for (int sub = 0; sub < 2; sub++) {
            const int kt = ktp * 2 + sub;
            const uint32_t buf = stg + (uint32_t)sub * FLS_SUB;

            if (kt * 64 <= wrow_max) {   // warp has at least one unmasked key
                // ---- S (log2 units) = (Q*0.125*log2e) K^T
                float s[8][4];
#pragma unroll
                for (int j = 0; j < 8; j++)
#pragma unroll
                    for (int k = 0; k < 4; k++) s[j][k] = 0.0f;
#pragma unroll
                for (int kn = 0; kn < 4; kn++) {
#pragma unroll
                    for (int ks = 0; ks < 4; ks++) {
                        uint32_t sw = sw128((uint32_t)((kn * 16 + lrow) * 128 + ks * 32 + lkb));
                        uint32_t kh4[4];
                        ldsm4(kh4, buf + sw);
                        mma16816(s[kn * 2],     qf[ks], kh4[0], kh4[2]);
                        mma16816(s[kn * 2 + 1], qf[ks], kh4[1], kh4[3]);
                    }
                }

                // ---- causal mask
                const int gr1 = qt * 128 + w * 16 + (lane >> 2);
                if (kt * 64 + 63 > qt * 128 + w * 16) {
#pragma unroll
                    for (int j = 0; j < 8; j++) {
                        int c = kt * 64 + j * 8 + (lane & 3) * 2;
                        if (c     > gr1)     s[j][0] = -1e30f;
                        if (c + 1 > gr1)     s[j][1] = -1e30f;
                        if (c     > gr1 + 8) s[j][2] = -1e30f;
                        if (c + 1 > gr1 + 8) s[j][3] = -1e30f;
                    }
                }

                // ---- online max (log2 domain)
                float mx1 = -1e30f, mx2 = -1e30f;
#pragma unroll
                for (int j = 0; j < 8; j++) {
                    mx1 = fmaxf(mx1, fmaxf(s[j][0], s[j][1]));
                    mx2 = fmaxf(mx2, fmaxf(s[j][2], s[j][3]));
                }
                mx1 = fmaxf(mx1, __shfl_xor_sync(0xffffffffu, mx1, 1));
                mx1 = fmaxf(mx1, __shfl_xor_sync(0xffffffffu, mx1, 2));
                mx2 = fmaxf(mx2, __shfl_xor_sync(0xffffffffu, mx2, 1));
                mx2 = fmaxf(mx2, __shfl_xor_sync(0xffffffffu, mx2, 2));
                float nm1 = fmaxf(m1, mx1), nm2 = fmaxf(m2, mx2);
                if (__any_sync(0xffffffffu, (nm1 > m1) || (nm2 > m2))) {
                    float a1 = exp2f(m1 - nm1), a2 = exp2f(m2 - nm2);
                    m1 = nm1; m2 = nm2;
#pragma unroll
                    for (int j = 0; j < 8; j++) {
                        o[j][0] *= a1; o[j][1] *= a1;
                        o[j][2] *= a2; o[j][3] *= a2;
                    }
                    l1 *= a1; l2 *= a2;
                }

                // ---- p = ex2(s - m); O += P V; row sums via ones-MMA
                float osum[4] = {0.0f, 0.0f, 0.0f, 0.0f};
                const int lg = lane >> 3, lr8 = lane & 7;
#pragma unroll
                for (int kn = 0; kn < 4; kn++) {
                    uint32_t ph[4];
                    ph[0] = ex2_h2(pack_h2(s[2 * kn][0] - m1, s[2 * kn][1] - m1));
                    ph[1] = ex2_h2(pack_h2(s[2 * kn][2] - m2, s[2 * kn][3] - m2));
                    ph[2] = ex2_h2(pack_h2(s[2 * kn + 1][0] - m1, s[2 * kn + 1][1] - m1));
                    ph[3] = ex2_h2(pack_h2(s[2 * kn + 1][2] - m2, s[2 * kn + 1][3] - m2));
                    mma16816(osum, ph, ones, ones);
#pragma unroll
                    for (int nd = 0; nd < 4; nd++) {
                        int key = kn * 16 + lr8 + (lg >> 1) * 8;
                        int dim = nd * 16 + (lg & 1) * 8;
                        uint32_t sw = sw128((uint32_t)(key * 128 + dim * 2));
                        uint32_t vh4[4];
                        ldsm4t(vh4, buf + FLS_VH + sw);
                        mma16816(o[nd * 2],     ph, vh4[0], vh4[2]);
                        mma16816(o[nd * 2 + 1], ph, vh4[1], vh4[3]);
                    }
                }
                l1 += osum[0];
                l2 += osum[2];
            }
        }

        CP_WAIT0();
        __syncthreads();
    }

    l1 = __shfl_sync(0xffffffffu, l1, lane & 28);
    l2 = __shfl_sync(0xffffffffu, l2, lane & 28);

    const int b = bh >> 4, hh = bh & 15;
    const int t1 = qt * 128 + w * 16 + (lane >> 2);
    const float inv1 = 1.0f / l1, inv2 = 1.0f / l2;
#pragma unroll
    for (int j = 0; j < 8; j++) {
        int d = j * 8 + (lane & 3) * 2;
        size_t i1 = ((size_t)(b * T_ + t1)) * C_ + hh * 64 + d;
        size_t i2 = i1 + (size_t)8 * C_;
        *(uint32_t*)&g_attnh[i1] = pack_h2(o[j][0] * inv1, o[j][1] * inv1);
        *(uint32_t*)&g_attnh[i2] = pack_h2(o[j][2] * inv2, o[j][3] * inv2);
    }
}

// ---------------------------------------------------------------------------
extern "C" void kernel_launch(void* const* d_in, const int* in_sizes, int n_in,
                              void* d_out, int out_size) {
    const float* x    = (const float*)d_in[0];
    const float* Wqkv = (const float*)d_in[1];
    const float* Wout = (const float*)d_in[2];
    const float* bout = (const float*)d_in[3];
    float* out = (float*)d_out;

    conv_x<<<(M_ * C_ + 255) / 256, 256>>>(x);
    conv_t2<<<dim3(NQKV_ / 32, C_ / 32, 2), dim3(32, 8)>>>(Wqkv, Wout);

    cudaFuncSetAttribute(hmma_gemm, cudaFuncAttributeMaxDynamicSharedMemorySize, GEMM_SMEM);
    hmma_gemm<<<dim3(NQKV_ / 128, M_ / 128), 256, GEMM_SMEM>>>(0, nullptr, nullptr, NQKV_);

    cudaFuncSetAttribute(hmma_flash, cudaFuncAttributeMaxDynamicSharedMemorySize, FL_SMEM);
    hmma_flash<<<dim3(T_ / 128, B_ * H_), 256, FL_SMEM>>>();

    hmma_gemm<<<dim3(C_ / 128, M_ / 128), 256, GEMM_SMEM>>>(1, out, bout, C_);
}

// round 15
// speedup vs baseline: 1.1085x; 1.0593x over previous
#include <cuda_runtime.h>
#include <cuda_fp16.h>
#include <cstdint>

#define B_  2
#define T_  2048
#define C_  1024
#define H_  16
#define M_  (B_*T_)      // 4096
#define NQKV_ (3*C_)     // 3072

// ---------------- device scratch (no allocation allowed) -------------------
__device__ __half g_xh[M_*C_];                       // x fp16
__device__ __half g_wqkvTh[NQKV_*C_];                // Wqkv^T fp16
__device__ __half g_woutTh[C_*C_];                   // Wout^T fp16
__device__ __half g_attnh[M_*C_];                    // attn out fp16
// [b,h,t,d]: q pre-scaled by 0.125*log2(e), k, v fp16
__device__ __half g_qh[M_*C_], g_kh[M_*C_], g_vh[M_*C_];

// ---------------- helpers ----------------------------------------------------
__device__ __forceinline__ uint32_t smem_u32_of(const void* p) {
    uint32_t a;
    asm("{ .reg .u64 t; cvta.to.shared.u64 t, %1; cvt.u32.u64 %0, t; }" : "=r"(a) : "l"(p));
    return a;
}
__device__ __forceinline__ void ldsm4(uint32_t* r, uint32_t addr) {
    asm volatile("ldmatrix.sync.aligned.m8n8.x4.shared.b16 {%0,%1,%2,%3}, [%4];"
                 : "=r"(r[0]), "=r"(r[1]), "=r"(r[2]), "=r"(r[3]) : "r"(addr));
}
__device__ __forceinline__ void ldsm4t(uint32_t* r, uint32_t addr) {
    asm volatile("ldmatrix.sync.aligned.m8n8.x4.trans.shared.b16 {%0,%1,%2,%3}, [%4];"
                 : "=r"(r[0]), "=r"(r[1]), "=r"(r[2]), "=r"(r[3]) : "r"(addr));
}
__device__ __forceinline__ void mma16816(float* c, const uint32_t* a,
                                         uint32_t b0, uint32_t b1) {
    asm volatile(
        "mma.sync.aligned.m16n8k16.row.col.f32.f16.f16.f32 "
        "{%0,%1,%2,%3}, {%4,%5,%6,%7}, {%8,%9}, {%0,%1,%2,%3};"
        : "+f"(c[0]), "+f"(c[1]), "+f"(c[2]), "+f"(c[3])
        : "r"(a[0]), "r"(a[1]), "r"(a[2]), "r"(a[3]), "r"(b0), "r"(b1));
}
#define CP16(dst, src) \
    asm volatile("cp.async.cg.shared.global [%0], [%1], 16;" :: "r"(dst), "l"(src) : "memory")
#define CP_COMMIT() asm volatile("cp.async.commit_group;" ::: "memory")
#define CP_WAIT0()  asm volatile("cp.async.wait_group 0;" ::: "memory")

__device__ __forceinline__ uint32_t sw128(uint32_t off) {
    return off ^ ((off >> 3) & 0x70);
}
__device__ __forceinline__ uint32_t pack_h2(float v0, float v1) {
    __half2 hp = __floats2half2_rn(v0, v1);
    return *(uint32_t*)&hp;
}
__device__ __forceinline__ uint32_t ex2_h2(uint32_t x) {
    uint32_t r;
    asm("ex2.approx.f16x2 %0, %1;" : "=r"(r) : "r"(x));
    return r;
}

// ---------------------------------------------------------------------------
// fp16 1-term HMMA GEMM (unchanged).
// ---------------------------------------------------------------------------
#define GS_A    0
#define GS_B    16384
#define GS_STAGE 32768
#define GEMM_SMEM 65536
#define NCHUNK 16

__device__ __forceinline__ void gemm_load_stage(
    uint32_t dst, int ch, int bm, int bn, int tid,
    const __half* Ah, const __half* Bh) {
    const int k0 = ch * 64;
#pragma unroll
    for (int i = tid; i < 1024; i += 256) {
        int r = i >> 3, g = i & 7;
        uint32_t sw = sw128((uint32_t)(r * 128 + g * 16));
        CP16(dst + GS_A + sw, Ah + (size_t)(bm + r) * C_ + k0 + g * 8);
        CP16(dst + GS_B + sw, Bh + (size_t)(bn + r) * C_ + k0 + g * 8);
    }
}

__global__ __launch_bounds__(256, 2) void hmma_gemm(int mode, float* __restrict__ out,
                                                    const float* __restrict__ bias, int N) {
    extern __shared__ char smem[];
    const uint32_t sbase = smem_u32_of(smem);
    const int tid = threadIdx.x, wid = tid >> 5, lane = tid & 31;
    const int bm = blockIdx.y * 128, bn = blockIdx.x * 128;
    const int wm = wid & 3, wn = wid >> 2;

    const __half* Ah = (mode == 0) ? g_xh : g_attnh;
    const __half* Bh = (mode == 0) ? g_wqkvTh : g_woutTh;

    float acc[2][8][4];
#pragma unroll
    for (int i = 0; i < 2; i++)
#pragma unroll
        for (int j = 0; j < 8; j++)
#pragma unroll
            for (int k = 0; k < 4; k++) acc[i][j][k] = 0.0f;

    const int lrow = lane & 15;
    const int lkb  = (lane >> 4) << 4;

    gemm_load_stage(sbase, 0, bm, bn, tid, Ah, Bh);
    CP_COMMIT();
    CP_WAIT0();
    __syncthreads();

    for (int ch = 0; ch < NCHUNK; ch++) {
        if (ch + 1 < NCHUNK) {
            gemm_load_stage(sbase + (uint32_t)((ch + 1) & 1) * GS_STAGE, ch + 1,
                            bm, bn, tid, Ah, Bh);
            CP_COMMIT();
        }
        const uint32_t buf = sbase + (uint32_t)(ch & 1) * GS_STAGE;

#pragma unroll
        for (int ks = 0; ks < 4; ks++) {
            uint32_t ah[2][4];
#pragma unroll
            for (int mf = 0; mf < 2; mf++) {
                uint32_t sw = sw128((uint32_t)((wm * 32 + mf * 16 + lrow) * 128 + ks * 32 + lkb));
                ldsm4(ah[mf], buf + GS_A + sw);
            }
#pragma unroll
            for (int np = 0; np < 4; np++) {
                uint32_t sw = sw128((uint32_t)((wn * 64 + np * 16 + lrow) * 128 + ks * 32 + lkb));
                uint32_t bh[4];
                ldsm4(bh, buf + GS_B + sw);
#pragma unroll
                for (int mf = 0; mf < 2; mf++) {
                    mma16816(acc[mf][np * 2],     ah[mf], bh[0], bh[2]);
                    mma16816(acc[mf][np * 2 + 1], ah[mf], bh[1], bh[3]);
                }
            }
        }
        CP_WAIT0();
        __syncthreads();
    }

    const int r0 = bm + wm * 32 + (lane >> 2);
    const int c0 = bn + wn * 64 + (lane & 3) * 2;
    if (mode == 0) {
#pragma unroll
        for (int nf = 0; nf < 8; nf++) {
            int col = c0 + nf * 8;
            int which = col >> 10;
            int hh = (col >> 6) & 15;
            int d = col & 63;
            float sc = (which == 0) ? 0.18033688011112042f : 1.0f;  // (1/8)*log2e
            __half* dst = (which == 0) ? g_qh : (which == 1) ? g_kh : g_vh;
#pragma unroll
            for (int mf = 0; mf < 2; mf++) {
                int row = r0 + mf * 16;
                int t = row & (T_ - 1), b = row >> 11;
                size_t i1 = ((size_t)((b << 4) + hh) * T_ + t) * 64 + d;
                *(uint32_t*)&dst[i1] = pack_h2(acc[mf][nf][0] * sc, acc[mf][nf][1] * sc);
                *(uint32_t*)&dst[i1 + 8 * 64] = pack_h2(acc[mf][nf][2] * sc, acc[mf][nf][3] * sc);
            }
        }
    } else {
#pragma unroll
        for (int mf = 0; mf < 2; mf++) {
#pragma unroll
            for (int nf = 0; nf < 8; nf++) {
                int row = r0 + mf * 16;
                int col = c0 + nf * 8;
                float b0 = bias[col], b1 = bias[col + 1];
                *(float2*)&out[(size_t)row * N + col] =
                    make_float2(acc[mf][nf][0] + b0, acc[mf][nf][1] + b1);
                *(float2*)&out[(size_t)(row + 8) * N + col] =
                    make_float2(acc[mf][nf][2] + b0, acc[mf][nf][3] + b1);
            }
        }
    }
}

// ---------------------------------------------------------------------------
__global__ void conv_x(const float* __restrict__ src) {
    int i = blockIdx.x * 256 + threadIdx.x;   // processes 4 floats
    if (i < M_ * C_ / 4) {
        float4 v = ((const float4*)src)[i];
        uint32_t lo = pack_h2(v.x, v.y), hi = pack_h2(v.z, v.w);
        ((uint2*)g_xh)[i] = make_uint2(lo, hi);
    }
}
__global__ void conv_t2(const float* __restrict__ wqkv, const float* __restrict__ wout) {
    __shared__ float s[32][33];
    const int z = blockIdx.z;
    const int N = z ? C_ : NQKV_;
    if (blockIdx.x * 32 >= N) return;
    const float* src = z ? wout : wqkv;
    __half* dst = z ? g_woutTh : g_wqkvTh;
    int n0 = blockIdx.x * 32, k0 = blockIdx.y * 32;
    int tx = threadIdx.x, ty = threadIdx.y;
#pragma unroll
    for (int yy = 0; yy < 32; yy += 8)
        s[ty + yy][tx] = src[(size_t)(k0 + ty + yy) * N + n0 + tx];
    __syncthreads();
#pragma unroll
    for (int yy = 0; yy < 32; yy += 8)
        dst[(size_t)(n0 + ty + yy) * C_ + k0 + tx] = __float2half(s[tx][ty + yy]);
}

// ---------------------------------------------------------------------------
// fp16 flash attention, log2-domain softmax with NO-SUBTRACT fast path:
//  m starts at 0; p = ex2(s) directly while all scores stay <= m+10 (the
//  universal case here).  Overflow guard per-lane (__any_sync, no shuffle
//  reduce in the fast path).  Rare trigger -> full reduce/rescale/subtract.
//  128 keys per pipeline stage; MMA row-sums; one sync per 128 keys.
// ---------------------------------------------------------------------------
#define FLS_SUB   16384
#define FLS_VH    8192
#define FLS_STAGE 32768
#define FLS_QH    65536
#define FL_SMEM   81920

// PV block: p = ex2(s - M1/M2) (M=0 constant-folds the subs), row-sum MMA, O += P·V
#define PV_BLOCK(M1, M2)                                                          \
    {                                                                             \
        const int lg = lane >> 3, lr8 = lane & 7;                                 \
        _Pragma("unroll")                                                         \
        for (int kn = 0; kn < 4; kn++) {                                          \
            uint32_t ph[4];                                                       \
            ph[0] = ex2_h2(pack_h2(s[2*kn][0]   - (M1), s[2*kn][1]   - (M1)));    \
            ph[1] = ex2_h2(pack_h2(s[2*kn][2]   - (M2), s[2*kn][3]   - (M2)));    \
            ph[2] = ex2_h2(pack_h2(s[2*kn+1][0] - (M1), s[2*kn+1][1] - (M1)));    \
            ph[3] = ex2_h2(pack_h2(s[2*kn+1][2] - (M2), s[2*kn+1][3] - (M2)));    \
            mma16816(osum, ph, ones, ones);                                       \
            _Pragma("unroll")                                                     \
            for (int nd = 0; nd < 4; nd++) {                                      \
                int key = kn * 16 + lr8 + (lg >> 1) * 8;                          \
                int dim = nd * 16 + (lg & 1) * 8;                                 \
                uint32_t sw = sw128((uint32_t)(key * 128 + dim * 2));             \
                uint32_t vh4[4];                                                  \
                ldsm4t(vh4, buf + FLS_VH + sw);                                   \
                mma16816(o[nd * 2],     ph, vh4[0], vh4[2]);                      \
                mma16816(o[nd * 2 + 1], ph, vh4[1], vh4[3]);                      \
            }                                                                     \
        }                                                                         \
    }

__device__ __forceinline__ void fl_load_pair(uint32_t dst, size_t gbase, int ktp, int tid) {
    const __half* kh = g_kh + gbase + (size_t)ktp * 128 * 64;
    const __half* vh = g_vh + gbase + (size_t)ktp * 128 * 64;
#pragma unroll
    for (int i = tid; i < 1024; i += 256) {
        int r = i >> 3, g = i & 7;
        int sub = r >> 6, rr = r & 63;
        uint32_t sw = (uint32_t)sub * FLS_SUB + sw128((uint32_t)(rr * 128 + g * 16));
        size_t go = (size_t)r * 64 + g * 8;
        CP16(dst + sw, kh + go);
        CP16(dst + FLS_VH + sw, vh + go);
    }
}

__global__ __launch_bounds__(256, 2) void hmma_flash() {
    extern __shared__ char smem[];
    const uint32_t sbase = smem_u32_of(smem);
    const int tid = threadIdx.x, w = tid >> 5, lane = tid & 31;
    const int qt = gridDim.x - 1 - blockIdx.x;   // heavy tiles first
    const int bh = blockIdx.y;
    const int nktp = qt + 1;
    const size_t gbase = (size_t)bh * T_ * 64;
    const int lrow = lane & 15, lkb = (lane >> 4) << 4;
    const uint32_t ones = (lane < 4) ? 0x3C003C00u : 0u;

    {
        const __half* qh = g_qh + gbase + (size_t)qt * 128 * 64;
#pragma unroll
        for (int i = tid; i < 1024; i += 256) {
            int r = i >> 3, g = i & 7;
            uint32_t sw = sw128((uint32_t)(r * 128 + g * 16));
            CP16(sbase + FLS_QH + sw, qh + (size_t)r * 64 + g * 8);
        }
    }
    fl_load_pair(sbase, gbase, 0, tid);
    CP_COMMIT();
    CP_WAIT0();
    __syncthreads();

    uint32_t qf[4][4];
#pragma unroll
    for (int ks = 0; ks < 4; ks++) {
        uint32_t sw = sw128((uint32_t)((w * 16 + lrow) * 128 + ks * 32 + lkb));
        ldsm4(qf[ks], sbase + FLS_QH + sw);
    }

    float o[8][4];
#pragma unroll
    for (int j = 0; j < 8; j++)
#pragma unroll
        for (int k = 0; k < 4; k++) o[j][k] = 0.0f;
    float m1 = 0.0f, m2 = 0.0f, l1 = 0.0f, l2 = 0.0f;   // m starts at 0 (no-sub fast path)

    const int wrow_max = qt * 128 + w * 16 + 15;

    for (int ktp = 0; ktp < nktp; ktp++) {
        if (ktp + 1 < nktp) {
            fl_load_pair(sbase + (uint32_t)((ktp + 1) & 1) * FLS_STAGE, gbase, ktp + 1, tid);
            CP_COMMIT();
        }
        const uint32_t stg = sbase + (uint32_t)(ktp & 1) * FLS_STAGE;

#pragma unroll
        for (int sub = 0; sub < 2; sub++) {
            const int kt = ktp * 2 + sub;
            const uint32_t buf = stg + (uint32_t)sub * FLS_SUB;

            if (kt * 64 <= wrow_max) {
                // ---- S (log2 units)
                float s[8][4];
#pragma unroll
                for (int j = 0; j < 8; j++)
#pragma unroll
                    for (int k = 0; k < 4; k++) s[j][k] = 0.0f;
#pragma unroll
                for (int kn = 0; kn < 4; kn++) {
#pragma unroll
                    for (int ks = 0; ks < 4; ks++) {
                        uint32_t sw = sw128((uint32_t)((kn * 16 + lrow) * 128 + ks * 32 + lkb));
                        uint32_t kh4[4];
                        ldsm4(kh4, buf + sw);
                        mma16816(s[kn * 2],     qf[ks], kh4[0], kh4[2]);
                        mma16816(s[kn * 2 + 1], qf[ks], kh4[1], kh4[3]);
                    }
                }

                // ---- causal mask
                const int gr1 = qt * 128 + w * 16 + (lane >> 2);
                if (kt * 64 + 63 > qt * 128 + w * 16) {
#pragma unroll
                    for (int j = 0; j < 8; j++) {
                        int c = kt * 64 + j * 8 + (lane & 3) * 2;
                        if (c     > gr1)     s[j][0] = -1e30f;
                        if (c + 1 > gr1)     s[j][1] = -1e30f;
                        if (c     > gr1 + 8) s[j][2] = -1e30f;
                        if (c + 1 > gr1 + 8) s[j][3] = -1e30f;
                    }
                }

                // ---- overflow guard (per-lane, no reduce in fast path)
                float mx1 = -1e30f, mx2 = -1e30f;
#pragma unroll
                for (int j = 0; j < 8; j++) {
                    mx1 = fmaxf(mx1, fmaxf(s[j][0], s[j][1]));
                    mx2 = fmaxf(mx2, fmaxf(s[j][2], s[j][3]));
                }
                bool trigger = __any_sync(0xffffffffu,
                                          (mx1 > m1 + 10.0f) || (mx2 > m2 + 10.0f));

                float osum[4] = {0.0f, 0.0f, 0.0f, 0.0f};
                if (!trigger) {
                    if (__all_sync(0xffffffffu, (m1 == 0.0f) && (m2 == 0.0f))) {
                        PV_BLOCK(0.0f, 0.0f)       // subs fold away
                    } else {
                        PV_BLOCK(m1, m2)
                    }
                } else {
                    // full reduce + rescale + subtract (rare)
                    mx1 = fmaxf(mx1, __shfl_xor_sync(0xffffffffu, mx1, 1));
                    mx1 = fmaxf(mx1, __shfl_xor_sync(0xffffffffu, mx1, 2));
                    mx2 = fmaxf(mx2, __shfl_xor_sync(0xffffffffu, mx2, 1));
                    mx2 = fmaxf(mx2, __shfl_xor_sync(0xffffffffu, mx2, 2));
                    float nm1 = fmaxf(m1, mx1), nm2 = fmaxf(m2, mx2);
                    float a1 = exp2f(m1 - nm1), a2 = exp2f(m2 - nm2);
                    m1 = nm1; m2 = nm2;
#pragma unroll
                    for (int j = 0; j < 8; j++) {
                        o[j][0] *= a1; o[j][1] *= a1;
                        o[j][2] *= a2; o[j][3] *= a2;
                    }
                    l1 *= a1; l2 *= a2;
                    PV_BLOCK(m1, m2)
                }
                l1 += osum[0];
                l2 += osum[2];
            }
        }

        CP_WAIT0();
        __syncthreads();
    }

    l1 = __shfl_sync(0xffffffffu, l1, lane & 28);
    l2 = __shfl_sync(0xffffffffu, l2, lane & 28);

    const int b = bh >> 4, hh = bh & 15;
    const int t1 = qt * 128 + w * 16 + (lane >> 2);
    const float inv1 = 1.0f / l1, inv2 = 1.0f / l2;
#pragma unroll
    for (int j = 0; j < 8; j++) {
        int d = j * 8 + (lane & 3) * 2;
        size_t i1 = ((size_t)(b * T_ + t1)) * C_ + hh * 64 + d;
        size_t i2 = i1 + (size_t)8 * C_;
        *(uint32_t*)&g_attnh[i1] = pack_h2(o[j][0] * inv1, o[j][1] * inv1);
        *(uint32_t*)&g_attnh[i2] = pack_h2(o[j][2] * inv2, o[j][3] * inv2);
    }
}

// ---------------------------------------------------------------------------
extern "C" void kernel_launch(void* const* d_in, const int* in_sizes, int n_in,
                              void* d_out, int out_size) {
    const float* x    = (const float*)d_in[0];
    const float* Wqkv = (const float*)d_in[1];
    const float* Wout = (const float*)d_in[2];
    const float* bout = (const float*)d_in[3];
    float* out = (float*)d_out;

    conv_x<<<(M_ * C_ / 4 + 255) / 256, 256>>>(x);
    conv_t2<<<dim3(NQKV_ / 32, C_ / 32, 2), dim3(32, 8)>>>(Wqkv, Wout);

    cudaFuncSetAttribute(hmma_gemm, cudaFuncAttributeMaxDynamicSharedMemorySize, GEMM_SMEM);
    hmma_gemm<<<dim3(NQKV_ / 128, M_ / 128), 256, GEMM_SMEM>>>(0, nullptr, nullptr, NQKV_);

    cudaFuncSetAttribute(hmma_flash, cudaFuncAttributeMaxDynamicSharedMemorySize, FL_SMEM);
    hmma_flash<<<dim3(T_ / 128, B_ * H_), 256, FL_SMEM>>>();

    hmma_gemm<<<dim3(C_ / 128, M_ / 128), 256, GEMM_SMEM>>>(1, out, bout, C_);
}

// round 16
// speedup vs baseline: 1.1203x; 1.0107x over previous
#include <cuda_runtime.h>
#include <cuda_fp16.h>
#include <cstdint>

#define B_  2
#define T_  2048
#define C_  1024
#define H_  16
#define M_  (B_*T_)      // 4096
#define NQKV_ (3*C_)     // 3072

// ---------------- device scratch (no allocation allowed) -------------------
__device__ __half g_xh[M_*C_];                       // x fp16
__device__ __half g_wqkvTh[NQKV_*C_];                // Wqkv^T fp16
__device__ __half g_woutTh[C_*C_];                   // Wout^T fp16
__device__ __half g_attnh[M_*C_];                    // attn out fp16
// [b,h,t,d]: q pre-scaled by 0.125*log2(e), k, v fp16
__device__ __half g_qh[M_*C_], g_kh[M_*C_], g_vh[M_*C_];

// ---------------- helpers ----------------------------------------------------
__device__ __forceinline__ uint32_t smem_u32_of(const void* p) {
    uint32_t a;
    asm("{ .reg .u64 t; cvta.to.shared.u64 t, %1; cvt.u32.u64 %0, t; }" : "=r"(a) : "l"(p));
    return a;
}
__device__ __forceinline__ void ldsm4(uint32_t* r, uint32_t addr) {
    asm volatile("ldmatrix.sync.aligned.m8n8.x4.shared.b16 {%0,%1,%2,%3}, [%4];"
                 : "=r"(r[0]), "=r"(r[1]), "=r"(r[2]), "=r"(r[3]) : "r"(addr));
}
__device__ __forceinline__ void ldsm4t(uint32_t* r, uint32_t addr) {
    asm volatile("ldmatrix.sync.aligned.m8n8.x4.trans.shared.b16 {%0,%1,%2,%3}, [%4];"
                 : "=r"(r[0]), "=r"(r[1]), "=r"(r[2]), "=r"(r[3]) : "r"(addr));
}
__device__ __forceinline__ void mma16816(float* c, const uint32_t* a,
                                         uint32_t b0, uint32_t b1) {
    asm volatile(
        "mma.sync.aligned.m16n8k16.row.col.f32.f16.f16.f32 "
        "{%0,%1,%2,%3}, {%4,%5,%6,%7}, {%8,%9}, {%0,%1,%2,%3};"
        : "+f"(c[0]), "+f"(c[1]), "+f"(c[2]), "+f"(c[3])
        : "r"(a[0]), "r"(a[1]), "r"(a[2]), "r"(a[3]), "r"(b0), "r"(b1));
}
#define CP16(dst, src) \
    asm volatile("cp.async.cg.shared.global [%0], [%1], 16;" :: "r"(dst), "l"(src) : "memory")
#define CP_COMMIT() asm volatile("cp.async.commit_group;" ::: "memory")
#define CP_WAIT1()  asm volatile("cp.async.wait_group 1;" ::: "memory")
#define CP_WAIT0()  asm volatile("cp.async.wait_group 0;" ::: "memory")

__device__ __forceinline__ uint32_t sw128(uint32_t off) {
    return off ^ ((off >> 3) & 0x70);
}
__device__ __forceinline__ uint32_t pack_h2(float v0, float v1) {
    __half2 hp = __floats2half2_rn(v0, v1);
    return *(uint32_t*)&hp;
}
__device__ __forceinline__ uint32_t ex2_h2(uint32_t x) {
    uint32_t r;
    asm("ex2.approx.f16x2 %0, %1;" : "=r"(r) : "r"(x));
    return r;
}

// ---------------------------------------------------------------------------
// fp16 1-term HMMA GEMM (unchanged).
// ---------------------------------------------------------------------------
#define GS_A    0
#define GS_B    16384
#define GS_STAGE 32768
#define GEMM_SMEM 65536
#define NCHUNK 16

__device__ __forceinline__ void gemm_load_stage(
    uint32_t dst, int ch, int bm, int bn, int tid,
    const __half* Ah, const __half* Bh) {
    const int k0 = ch * 64;
#pragma unroll
    for (int i = tid; i < 1024; i += 256) {
        int r = i >> 3, g = i & 7;
        uint32_t sw = sw128((uint32_t)(r * 128 + g * 16));
        CP16(dst + GS_A + sw, Ah + (size_t)(bm + r) * C_ + k0 + g * 8);
        CP16(dst + GS_B + sw, Bh + (size_t)(bn + r) * C_ + k0 + g * 8);
    }
}

__global__ __launch_bounds__(256, 2) void hmma_gemm(int mode, float* __restrict__ out,
                                                    const float* __restrict__ bias, int N) {
    extern __shared__ char smem[];
    const uint32_t sbase = smem_u32_of(smem);
    const int tid = threadIdx.x, wid = tid >> 5, lane = tid & 31;
    const int bm = blockIdx.y * 128, bn = blockIdx.x * 128;
    const int wm = wid & 3, wn = wid >> 2;

    const __half* Ah = (mode == 0) ? g_xh : g_attnh;
    const __half* Bh = (mode == 0) ? g_wqkvTh : g_woutTh;

    float acc[2][8][4];
#pragma unroll
    for (int i = 0; i < 2; i++)
#pragma unroll
        for (int j = 0; j < 8; j++)
#pragma unroll
            for (int k = 0; k < 4; k++) acc[i][j][k] = 0.0f;

    const int lrow = lane & 15;
    const int lkb  = (lane >> 4) << 4;

    gemm_load_stage(sbase, 0, bm, bn, tid, Ah, Bh);
    CP_COMMIT();
    CP_WAIT0();
    __syncthreads();

    for (int ch = 0; ch < NCHUNK; ch++) {
        if (ch + 1 < NCHUNK) {
            gemm_load_stage(sbase + (uint32_t)((ch + 1) & 1) * GS_STAGE, ch + 1,
                            bm, bn, tid, Ah, Bh);
            CP_COMMIT();
        }
        const uint32_t buf = sbase + (uint32_t)(ch & 1) * GS_STAGE;

#pragma unroll
        for (int ks = 0; ks < 4; ks++) {
            uint32_t ah[2][4];
#pragma unroll
            for (int mf = 0; mf < 2; mf++) {
                uint32_t sw = sw128((uint32_t)((wm * 32 + mf * 16 + lrow) * 128 + ks * 32 + lkb));
                ldsm4(ah[mf], buf + GS_A + sw);
            }
#pragma unroll
            for (int np = 0; np < 4; np++) {
                uint32_t sw = sw128((uint32_t)((wn * 64 + np * 16 + lrow) * 128 + ks * 32 + lkb));
                uint32_t bh[4];
                ldsm4(bh, buf + GS_B + sw);
#pragma unroll
                for (int mf = 0; mf < 2; mf++) {
                    mma16816(acc[mf][np * 2],     ah[mf], bh[0], bh[2]);
                    mma16816(acc[mf][np * 2 + 1], ah[mf], bh[1], bh[3]);
                }
            }
        }
        CP_WAIT0();
        __syncthreads();
    }

    const int r0 = bm + wm * 32 + (lane >> 2);
    const int c0 = bn + wn * 64 + (lane & 3) * 2;
    if (mode == 0) {
#pragma unroll
        for (int nf = 0; nf < 8; nf++) {
            int col = c0 + nf * 8;
            int which = col >> 10;
            int hh = (col >> 6) & 15;
            int d = col & 63;
            float sc = (which == 0) ? 0.18033688011112042f : 1.0f;  // (1/8)*log2e
            __half* dst = (which == 0) ? g_qh : (which == 1) ? g_kh : g_vh;
#pragma unroll
            for (int mf = 0; mf < 2; mf++) {
                int row = r0 + mf * 16;
                int t = row & (T_ - 1), b = row >> 11;
                size_t i1 = ((size_t)((b << 4) + hh) * T_ + t) * 64 + d;
                *(uint32_t*)&dst[i1] = pack_h2(acc[mf][nf][0] * sc, acc[mf][nf][1] * sc);
                *(uint32_t*)&dst[i1 + 8 * 64] = pack_h2(acc[mf][nf][2] * sc, acc[mf][nf][3] * sc);
            }
        }
    } else {
#pragma unroll
        for (int mf = 0; mf < 2; mf++) {
#pragma unroll
            for (int nf = 0; nf < 8; nf++) {
                int row = r0 + mf * 16;
                int col = c0 + nf * 8;
                float b0 = bias[col], b1 = bias[col + 1];
                *(float2*)&out[(size_t)row * N + col] =
                    make_float2(acc[mf][nf][0] + b0, acc[mf][nf][1] + b1);
                *(float2*)&out[(size_t)(row + 8) * N + col] =
                    make_float2(acc[mf][nf][2] + b0, acc[mf][nf][3] + b1);
            }
        }
    }
}

// ---------------------------------------------------------------------------
// merged conversions: z=0 Wqkv^T, z=1 Wout^T, z=2 x fp32->fp16 (grid-stride)
// ---------------------------------------------------------------------------
__global__ void conv_all(const float* __restrict__ x,
                         const float* __restrict__ wqkv,
                         const float* __restrict__ wout) {
    const int z = blockIdx.z;
    const int tx = threadIdx.x, ty = threadIdx.y;
    if (z == 2) {
        int idx = (blockIdx.y * gridDim.x + blockIdx.x) * 256 + ty * 32 + tx;
        const int stride = gridDim.x * gridDim.y * 256;
        for (int i = idx; i < M_ * C_ / 4; i += stride) {
            float4 v = ((const float4*)x)[i];
            ((uint2*)g_xh)[i] = make_uint2(pack_h2(v.x, v.y), pack_h2(v.z, v.w));
        }
        return;
    }
    __shared__ float s[32][33];
    const int N = z ? C_ : NQKV_;
    if (blockIdx.x * 32 >= N) return;
    const float* src = z ? wout : wqkv;
    __half* dst = z ? g_woutTh : g_wqkvTh;
    int n0 = blockIdx.x * 32, k0 = blockIdx.y * 32;
#pragma unroll
    for (int yy = 0; yy < 32; yy += 8)
        s[ty + yy][tx] = src[(size_t)(k0 + ty + yy) * N + n0 + tx];
    __syncthreads();
#pragma unroll
    for (int yy = 0; yy < 32; yy += 8)
        dst[(size_t)(n0 + ty + yy) * C_ + k0 + tx] = __float2half(s[tx][ty + yy]);
}

// ---------------------------------------------------------------------------
// fp16 flash attention: log2-domain no-subtract softmax, 128-key pairs,
// THREE-stage cp.async pipeline (stage 32K x3 + Q 16K = 112K; 2 CTA/SM).
// ---------------------------------------------------------------------------
#define FLS_SUB   16384
#define FLS_VH    8192
#define FLS_STAGE 32768
#define FLS_QH    98304
#define FL_SMEM   114688

#define PV_BLOCK(M1, M2)                                                          \
    {                                                                             \
        const int lg = lane >> 3, lr8 = lane & 7;                                 \
        _Pragma("unroll")                                                         \
        for (int kn = 0; kn < 4; kn++) {                                          \
            uint32_t ph[4];                                                       \
            ph[0] = ex2_h2(pack_h2(s[2*kn][0]   - (M1), s[2*kn][1]   - (M1)));    \
            ph[1] = ex2_h2(pack_h2(s[2*kn][2]   - (M2), s[2*kn][3]   - (M2)));    \
            ph[2] = ex2_h2(pack_h2(s[2*kn+1][0] - (M1), s[2*kn+1][1] - (M1)));    \
            ph[3] = ex2_h2(pack_h2(s[2*kn+1][2] - (M2), s[2*kn+1][3] - (M2)));    \
            mma16816(osum, ph, ones, ones);                                       \
            _Pragma("unroll")                                                     \
            for (int nd = 0; nd < 4; nd++) {                                      \
                int key = kn * 16 + lr8 + (lg >> 1) * 8;                          \
                int dim = nd * 16 + (lg & 1) * 8;                                 \
                uint32_t sw = sw128((uint32_t)(key * 128 + dim * 2));             \
                uint32_t vh4[4];                                                  \
                ldsm4t(vh4, buf + FLS_VH + sw);                                   \
                mma16816(o[nd * 2],     ph, vh4[0], vh4[2]);                      \
                mma16816(o[nd * 2 + 1], ph, vh4[1], vh4[3]);                      \
            }                                                                     \
        }                                                                         \
    }

__device__ __forceinline__ void fl_load_pair(uint32_t dst, size_t gbase, int ktp, int tid) {
    const __half* kh = g_kh + gbase + (size_t)ktp * 128 * 64;
    const __half* vh = g_vh + gbase + (size_t)ktp * 128 * 64;
#pragma unroll
    for (int i = tid; i < 1024; i += 256) {
        int r = i >> 3, g = i & 7;
        int sub = r >> 6, rr = r & 63;
        uint32_t sw = (uint32_t)sub * FLS_SUB + sw128((uint32_t)(rr * 128 + g * 16));
        size_t go = (size_t)r * 64 + g * 8;
        CP16(dst + sw, kh + go);
        CP16(dst + FLS_VH + sw, vh + go);
    }
}

__global__ __launch_bounds__(256, 2) void hmma_flash() {
    extern __shared__ char smem[];
    const uint32_t sbase = smem_u32_of(smem);
    const int tid = threadIdx.x, w = tid >> 5, lane = tid & 31;
    const int qt = gridDim.x - 1 - blockIdx.x;   // heavy tiles first
    const int bh = blockIdx.y;
    const int nktp = qt + 1;
    const size_t gbase = (size_t)bh * T_ * 64;
    const int lrow = lane & 15, lkb = (lane >> 4) << 4;
    const uint32_t ones = (lane < 4) ? 0x3C003C00u : 0u;

    // group A: Q + pair0;  group B: pair1 (if any)
    {
        const __half* qh = g_qh + gbase + (size_t)qt * 128 * 64;
#pragma unroll
        for (int i = tid; i < 1024; i += 256) {
            int r = i >> 3, g = i & 7;
            uint32_t sw = sw128((uint32_t)(r * 128 + g * 16));
            CP16(sbase + FLS_QH + sw, qh + (size_t)r * 64 + g * 8);
        }
    }
    fl_load_pair(sbase, gbase, 0, tid);
    CP_COMMIT();
    if (nktp > 1) {
        fl_load_pair(sbase + FLS_STAGE, gbase, 1, tid);
        CP_COMMIT();
        CP_WAIT1();          // group A (Q + pair0) complete
    } else {
        CP_WAIT0();
    }
    __syncthreads();

    uint32_t qf[4][4];
#pragma unroll
    for (int ks = 0; ks < 4; ks++) {
        uint32_t sw = sw128((uint32_t)((w * 16 + lrow) * 128 + ks * 32 + lkb));
        ldsm4(qf[ks], sbase + FLS_QH + sw);
    }

    float o[8][4];
#pragma unroll
    for (int j = 0; j < 8; j++)
#pragma unroll
        for (int k = 0; k < 4; k++) o[j][k] = 0.0f;
    float m1 = 0.0f, m2 = 0.0f, l1 = 0.0f, l2 = 0.0f;

    const int wrow_max = qt * 128 + w * 16 + 15;

    for (int ktp = 0; ktp < nktp; ktp++) {
        if (ktp + 2 < nktp) {
            fl_load_pair(sbase + (uint32_t)((ktp + 2) % 3) * FLS_STAGE, gbase, ktp + 2, tid);
            CP_COMMIT();
        }
        const uint32_t stg = sbase + (uint32_t)(ktp % 3) * FLS_STAGE;

#pragma unroll
        for (int sub = 0; sub < 2; sub++) {
            const int kt = ktp * 2 + sub;
            const uint32_t buf = stg + (uint32_t)sub * FLS_SUB;

            if (kt * 64 <= wrow_max) {
                float s[8][4];
#pragma unroll
                for (int j = 0; j < 8; j++)
#pragma unroll
                    for (int k = 0; k < 4; k++) s[j][k] = 0.0f;
#pragma unroll
                for (int kn = 0; kn < 4; kn++) {
#pragma unroll
                    for (int ks = 0; ks < 4; ks++) {
                        uint32_t sw = sw128((uint32_t)((kn * 16 + lrow) * 128 + ks * 32 + lkb));
                        uint32_t kh4[4];
                        ldsm4(kh4, buf + sw);
                        mma16816(s[kn * 2],     qf[ks], kh4[0], kh4[2]);
                        mma16816(s[kn * 2 + 1], qf[ks], kh4[1], kh4[3]);
                    }
                }

                const int gr1 = qt * 128 + w * 16 + (lane >> 2);
                if (kt * 64 + 63 > qt * 128 + w * 16) {
#pragma unroll
                    for (int j = 0; j < 8; j++) {
                        int c = kt * 64 + j * 8 + (lane & 3) * 2;
                        if (c     > gr1)     s[j][0] = -1e30f;
                        if (c + 1 > gr1)     s[j][1] = -1e30f;
                        if (c     > gr1 + 8) s[j][2] = -1e30f;
                        if (c + 1 > gr1 + 8) s[j][3] = -1e30f;
                    }
                }

                float mx1 = -1e30f, mx2 = -1e30f;
#pragma unroll
                for (int j = 0; j < 8; j++) {
                    mx1 = fmaxf(mx1, fmaxf(s[j][0], s[j][1]));
                    mx2 = fmaxf(mx2, fmaxf(s[j][2], s[j][3]));
                }
                bool trigger = __any_sync(0xffffffffu,
                                          (mx1 > m1 + 10.0f) || (mx2 > m2 + 10.0f));

                float osum[4] = {0.0f, 0.0f, 0.0f, 0.0f};
                if (!trigger) {
                    if (__all_sync(0xffffffffu, (m1 == 0.0f) && (m2 == 0.0f))) {
                        PV_BLOCK(0.0f, 0.0f)
                    } else {
                        PV_BLOCK(m1, m2)
                    }
                } else {
                    mx1 = fmaxf(mx1, __shfl_xor_sync(0xffffffffu, mx1, 1));
                    mx1 = fmaxf(mx1, __shfl_xor_sync(0xffffffffu, mx1, 2));
                    mx2 = fmaxf(mx2, __shfl_xor_sync(0xffffffffu, mx2, 1));
                    mx2 = fmaxf(mx2, __shfl_xor_sync(0xffffffffu, mx2, 2));
                    float nm1 = fmaxf(m1, mx1), nm2 = fmaxf(m2, mx2);
                    float a1 = exp2f(m1 - nm1), a2 = exp2f(m2 - nm2);
                    m1 = nm1; m2 = nm2;
#pragma unroll
                    for (int j = 0; j < 8; j++) {
                        o[j][0] *= a1; o[j][1] *= a1;
                        o[j][2] *= a2; o[j][3] *= a2;
                    }
                    l1 *= a1; l2 *= a2;
                    PV_BLOCK(m1, m2)
                }
                l1 += osum[0];
                l2 += osum[2];
            }
        }

        if (ktp + 2 < nktp) { CP_WAIT1(); } else { CP_WAIT0(); }
        __syncthreads();
    }

    l1 = __shfl_sync(0xffffffffu, l1, lane & 28);
    l2 = __shfl_sync(0xffffffffu, l2, lane & 28);

    const int b = bh >> 4, hh = bh & 15;
    const int t1 = qt * 128 + w * 16 + (lane >> 2);
    const float inv1 = 1.0f / l1, inv2 = 1.0f / l2;
#pragma unroll
    for (int j = 0; j < 8; j++) {
        int d = j * 8 + (lane & 3) * 2;
        size_t i1 = ((size_t)(b * T_ + t1)) * C_ + hh * 64 + d;
        size_t i2 = i1 + (size_t)8 * C_;
        *(uint32_t*)&g_attnh[i1] = pack_h2(o[j][0] * inv1, o[j][1] * inv1);
        *(uint32_t*)&g_attnh[i2] = pack_h2(o[j][2] * inv2, o[j][3] * inv2);
    }
}

// ---------------------------------------------------------------------------
extern "C" void kernel_launch(void* const* d_in, const int* in_sizes, int n_in,
                              void* d_out, int out_size) {
    const float* x    = (const float*)d_in[0];
    const float* Wqkv = (const float*)d_in[1];
    const float* Wout = (const float*)d_in[2];
    const float* bout = (const float*)d_in[3];
    float* out = (float*)d_out;

    conv_all<<<dim3(NQKV_ / 32, C_ / 32, 3), dim3(32, 8)>>>(x, Wqkv, Wout);

    cudaFuncSetAttribute(hmma_gemm, cudaFuncAttributeMaxDynamicSharedMemorySize, GEMM_SMEM);
    hmma_gemm<<<dim3(NQKV_ / 128, M_ / 128), 256, GEMM_SMEM>>>(0, nullptr, nullptr, NQKV_);

    cudaFuncSetAttribute(hmma_flash, cudaFuncAttributeMaxDynamicSharedMemorySize, FL_SMEM);
    hmma_flash<<<dim3(T_ / 128, B_ * H_), 256, FL_SMEM>>>();

    hmma_gemm<<<dim3(C_ / 128, M_ / 128), 256, GEMM_SMEM>>>(1, out, bout, C_);
}